// round 11
// baseline (speedup 1.0000x reference)
#include <cuda_runtime.h>
#include <cuda_bf16.h>
#include <cstdint>
#include <math.h>

#define BB 2
#define SS 2048
#define EE 1024
#define HH 16
#define DD 64
#define MT 4096          // rows per GEMM (B*S)

// ---------------- scratch (__device__ globals; no allocs allowed) ----------------
__device__ __nv_bfloat16 g_Ahi[3*MT*EE];     // q,k,v activations hi
__device__ __nv_bfloat16 g_Alo[3*MT*EE];     // residual lo
__device__ __nv_bfloat16 g_Whi[4*EE*EE];     // W^T rows: [0,3072)=qkv, [3072,4096)=out
__device__ __nv_bfloat16 g_Wlo[4*EE*EE];

__device__ __nv_bfloat16 g_Qhi[BB*HH*SS*DD]; // pre-scaled by 0.125*log2(e), [b,h][s][d]
__device__ __nv_bfloat16 g_Qlo[BB*HH*SS*DD];
__device__ __nv_bfloat16 g_Khi[BB*HH*SS*DD]; // [b,h][s][d]
__device__ __nv_bfloat16 g_Klo[BB*HH*SS*DD];
__device__ __nv_bfloat16 g_VThi[BB*HH*DD*SS]; // transposed: [b,h][d][s]
__device__ __nv_bfloat16 g_VTlo[BB*HH*DD*SS];

__device__ __nv_bfloat16 g_Chi[MT*EE];       // ctx hi   [b,s][e]
__device__ __nv_bfloat16 g_Clo[MT*EE];
__device__ uint32_t g_mb[SS*(SS/32)];        // mask bits [q][kword]

// ---------------- helpers ----------------
__device__ __forceinline__ uint32_t smem_u32(const void* p) {
    uint32_t a;
    asm("{ .reg .u64 t; cvta.to.shared.u64 t, %1; cvt.u32.u64 %0, t; }" : "=r"(a) : "l"(p));
    return a;
}
__device__ __forceinline__ uint32_t sw128(uint32_t off) { return off ^ ((off >> 3) & 0x70); }
__device__ __forceinline__ uint32_t sw256(uint32_t off) { return off ^ ((off >> 4) & 0x70); }

__device__ __forceinline__ void cp_async16(uint32_t dst, const void* src) {
    asm volatile("cp.async.cg.shared.global [%0], [%1], 16;" :: "r"(dst), "l"(src) : "memory");
}
__device__ __forceinline__ void cp_commit() {
    asm volatile("cp.async.commit_group;" ::: "memory");
}
template <int N> __device__ __forceinline__ void cp_wait() {
    asm volatile("cp.async.wait_group %0;" :: "n"(N) : "memory");
}
__device__ __forceinline__ void ldsm_x4(uint32_t addr, uint32_t& r0, uint32_t& r1, uint32_t& r2, uint32_t& r3) {
    asm volatile("ldmatrix.sync.aligned.m8n8.x4.shared.b16 {%0,%1,%2,%3}, [%4];"
        : "=r"(r0), "=r"(r1), "=r"(r2), "=r"(r3) : "r"(addr));
}
__device__ __forceinline__ void mma16816(float* c, const uint32_t* a, uint32_t b0, uint32_t b1) {
    asm volatile("mma.sync.aligned.m16n8k16.row.col.f32.bf16.bf16.f32 "
        "{%0,%1,%2,%3}, {%4,%5,%6,%7}, {%8,%9}, {%0,%1,%2,%3};"
        : "+f"(c[0]), "+f"(c[1]), "+f"(c[2]), "+f"(c[3])
        : "r"(a[0]), "r"(a[1]), "r"(a[2]), "r"(a[3]), "r"(b0), "r"(b1));
}

// ---------------- conversion kernels ----------------
__global__ __launch_bounds__(256) void conv_rows3(
    const float* __restrict__ q, const float* __restrict__ k, const float* __restrict__ v,
    __nv_bfloat16* __restrict__ dhi, __nv_bfloat16* __restrict__ dlo)
{
    const int z = blockIdx.y;
    const float* src = (z == 0) ? q : (z == 1) ? k : v;
    size_t base = (size_t)z * MT * EE;
    int idx = blockIdx.x * 256 + threadIdx.x;
    float4 x = ((const float4*)src)[idx];
    __nv_bfloat16 hh[4], ll[4];
    float xs[4] = {x.x, x.y, x.z, x.w};
    #pragma unroll
    for (int i = 0; i < 4; i++) {
        hh[i] = __float2bfloat16(xs[i]);
        ll[i] = __float2bfloat16(xs[i] - __bfloat162float(hh[i]));
    }
    *(uint2*)&dhi[base + (size_t)idx * 4] = *(uint2*)hh;
    *(uint2*)&dlo[base + (size_t)idx * 4] = *(uint2*)ll;
}

__global__ __launch_bounds__(256) void conv_wT(
    const float* __restrict__ W, int ldn,
    __nv_bfloat16* __restrict__ dhi, __nv_bfloat16* __restrict__ dlo)
{
    __shared__ float t[32][33];
    const int n0 = blockIdx.x * 32;
    const int k0 = blockIdx.y * 32;
    const int tid = threadIdx.x;
    {
        int tx = tid & 31, ty = tid >> 5;
        #pragma unroll
        for (int r = 0; r < 4; r++) {
            int k = ty + r * 8;
            t[tx][k] = W[(size_t)(k0 + k) * ldn + n0 + tx];
        }
    }
    __syncthreads();
    {
        int tkg = tid & 7, tn = tid >> 3;
        __nv_bfloat16 hh[4], ll[4];
        #pragma unroll
        for (int i = 0; i < 4; i++) {
            float v = t[tn][tkg * 4 + i];
            hh[i] = __float2bfloat16(v);
            ll[i] = __float2bfloat16(v - __bfloat162float(hh[i]));
        }
        size_t off = (size_t)(n0 + tn) * EE + k0 + tkg * 4;
        *(uint2*)&dhi[off] = *(uint2*)hh;
        *(uint2*)&dlo[off] = *(uint2*)ll;
    }
}

// mask [S][S] int32 -> bit words. int4 loads, nibble pack in smem.
__global__ __launch_bounds__(256) void mask_bits(const int* __restrict__ mask)
{
    __shared__ unsigned char sn[256];
    int t = blockIdx.x * 256 + threadIdx.x;
    int4 x = ((const int4*)mask)[t];
    unsigned nib = (unsigned)(x.x != 0) | ((unsigned)(x.y != 0) << 1)
                 | ((unsigned)(x.z != 0) << 2) | ((unsigned)(x.w != 0) << 3);
    sn[threadIdx.x] = (unsigned char)nib;
    __syncthreads();
    if (threadIdx.x < 32) {
        unsigned w = 0;
        #pragma unroll
        for (int k = 0; k < 8; k++)
            w |= (unsigned)sn[threadIdx.x * 8 + k] << (4 * k);
        g_mb[blockIdx.x * 32 + threadIdx.x] = w;
    }
}

// ---------------- HMMA GEMM, 256x128 tile, 2-stage ----------------
#define Bb 256               // M tile
#define TILE_A 32768         // 256 rows x 128B
#define TILE_W 16384         // 128 rows x 128B
#define BUF_B  (2 * TILE_A + 2 * TILE_W)   // 98304
#define GEMM_SMEM (2 * BUF_B)              // 196608
#define NCHUNK 16

template <int MODE>
__global__ __launch_bounds__(256, 1) void mma_gemm(
    const __nv_bfloat16* __restrict__ Ahi, const __nv_bfloat16* __restrict__ Alo,
    const float* __restrict__ bias_all, float* __restrict__ out1)
{
    extern __shared__ char smem[];
    const uint32_t sb = smem_u32(smem);
    const int tid = threadIdx.x;
    const int wid = tid >> 5;
    const int lane = tid & 31;
    const int warp_m = wid & 3;      // 4 warps over 256 rows (64 each)
    const int warp_n = wid >> 2;     // 2 warps over 128 cols (64 each)

    const int n0 = blockIdx.x * 128;
    const int m0 = blockIdx.y * Bb;
    int z = 0, wbase;
    if (MODE == 0) { z = blockIdx.z; wbase = z * EE; } else { wbase = 3 * EE; }

    const uint4* gA0 = (const uint4*)(Ahi + ((MODE == 0) ? (size_t)z * MT * EE : 0) + (size_t)m0 * EE);
    const uint4* gA1 = (const uint4*)(Alo + ((MODE == 0) ? (size_t)z * MT * EE : 0) + (size_t)m0 * EE);
    const uint4* gB0 = (const uint4*)(g_Whi + (size_t)(wbase + n0) * EE);
    const uint4* gB1 = (const uint4*)(g_Wlo + (size_t)(wbase + n0) * EE);

    float acc[4][8][4];
    #pragma unroll
    for (int mt = 0; mt < 4; mt++)
        #pragma unroll
        for (int nt = 0; nt < 8; nt++)
            #pragma unroll
            for (int i = 0; i < 4; i++) acc[mt][nt][i] = 0.f;

    const int lr = tid >> 3;   // 0..31
    const int lj = tid & 7;    // 0..7

    auto load_chunk = [&](int c) {
        const uint32_t bbase = sb + (c & 1) * BUF_B;
        #pragma unroll
        for (int u = 0; u < 8; u++) {
            int r = lr + u * 32;
            uint32_t off = sw128((uint32_t)(r * 128 + lj * 16));
            cp_async16(bbase + 0 * TILE_A + off, gA0 + (size_t)r * 128 + c * 8 + lj);
            cp_async16(bbase + 1 * TILE_A + off, gA1 + (size_t)r * 128 + c * 8 + lj);
        }
        #pragma unroll
        for (int u = 0; u < 4; u++) {
            int r = lr + u * 32;
            uint32_t off = sw128((uint32_t)(r * 128 + lj * 16));
            cp_async16(bbase + 2 * TILE_A + 0 * TILE_W + off, gB0 + (size_t)r * 128 + c * 8 + lj);
            cp_async16(bbase + 2 * TILE_A + 1 * TILE_W + off, gB1 + (size_t)r * 128 + c * 8 + lj);
        }
        cp_commit();
    };

    load_chunk(0);

    for (int c = 0; c < NCHUNK; c++) {
        if (c + 1 < NCHUNK) { load_chunk(c + 1); cp_wait<1>(); }
        else                { cp_wait<0>(); }
        __syncthreads();

        const uint32_t bbase = sb + (c & 1) * BUF_B;
        #pragma unroll
        for (int kk = 0; kk < 4; kk++) {
            uint32_t ah[4][4], al2[4][4];
            #pragma unroll
            for (int mt = 0; mt < 4; mt++) {
                int row = warp_m * 64 + mt * 16 + (lane & 15);
                int ch  = kk * 2 + (lane >> 4);
                uint32_t off = sw128((uint32_t)(row * 128 + ch * 16));
                ldsm_x4(bbase + 0 * TILE_A + off, ah[mt][0], ah[mt][1], ah[mt][2], ah[mt][3]);
                ldsm_x4(bbase + 1 * TILE_A + off, al2[mt][0], al2[mt][1], al2[mt][2], al2[mt][3]);
            }
            #pragma unroll
            for (int p = 0; p < 4; p++) {
                int nr = warp_n * 64 + p * 16 + ((lane & 7) | ((lane & 16) >> 1));
                int ch = kk * 2 + ((lane >> 3) & 1);
                uint32_t off = sw128((uint32_t)(nr * 128 + ch * 16));
                uint32_t bh4[4], bl4[4];
                ldsm_x4(bbase + 2 * TILE_A + 0 * TILE_W + off, bh4[0], bh4[1], bh4[2], bh4[3]);
                ldsm_x4(bbase + 2 * TILE_A + 1 * TILE_W + off, bl4[0], bl4[1], bl4[2], bl4[3]);
                #pragma unroll
                for (int mt = 0; mt < 4; mt++) {
                    #pragma unroll
                    for (int half = 0; half < 2; half++) {
                        const int nt = p * 2 + half;
                        mma16816(acc[mt][nt], ah[mt],  bh4[half * 2], bh4[half * 2 + 1]);
                        mma16816(acc[mt][nt], ah[mt],  bl4[half * 2], bl4[half * 2 + 1]);
                        mma16816(acc[mt][nt], al2[mt], bh4[half * 2], bh4[half * 2 + 1]);
                    }
                }
            }
        }
        __syncthreads();
    }

    // ---------------- epilogue ----------------
    if (MODE == 0) {
        const float* bias = bias_all + z * EE;
        if (z == 2) {
            // stage through smem (f32), write VT coalesced
            float* st = (float*)smem;
            const int STR = 264;
            #pragma unroll
            for (int mt = 0; mt < 4; mt++) {
                #pragma unroll
                for (int nt = 0; nt < 8; nt++) {
                    const int col_l = warp_n * 64 + nt * 8 + (lane & 3) * 2;
                    const float bx = bias[n0 + col_l], by = bias[n0 + col_l + 1];
                    #pragma unroll
                    for (int half = 0; half < 2; half++) {
                        const int row_l = warp_m * 64 + mt * 16 + (lane >> 2) + half * 8;
                        st[col_l * STR + row_l]       = acc[mt][nt][half * 2 + 0] + bx;
                        st[(col_l + 1) * STR + row_l] = acc[mt][nt][half * 2 + 1] + by;
                    }
                }
            }
            __syncthreads();
            const int nl = tid >> 1;
            const int mh = (tid & 1) * 128;
            const int col = n0 + nl;
            const int h = col >> 6, d = col & 63;
            const int row0g = m0 + mh;
            const int bbv = row0g >> 11, s0 = row0g & (SS - 1);
            size_t base = ((size_t)(bbv * HH + h) * DD + d) * SS + s0;
            const float* srow = st + nl * STR + mh;
            #pragma unroll
            for (int i = 0; i < 128; i += 4) {
                float4 xv = *(const float4*)(srow + i);
                __nv_bfloat16 h4[4], l4[4];
                float xs[4] = {xv.x, xv.y, xv.z, xv.w};
                #pragma unroll
                for (int j = 0; j < 4; j++) {
                    h4[j] = __float2bfloat16(xs[j]);
                    l4[j] = __float2bfloat16(xs[j] - __bfloat162float(h4[j]));
                }
                *(uint2*)(g_VThi + base + i) = *(uint2*)h4;
                *(uint2*)(g_VTlo + base + i) = *(uint2*)l4;
            }
        } else {
            // Q pre-scale folds 1/sqrt(D) AND log2(e) so attention uses exp2 directly.
            const float qscale = 0.125f * 1.44269504f;
            #pragma unroll
            for (int mt = 0; mt < 4; mt++) {
                #pragma unroll
                for (int nt = 0; nt < 8; nt++) {
                    const int col = n0 + warp_n * 64 + nt * 8 + (lane & 3) * 2;
                    const int hh2 = col >> 6, dd2 = col & 63;
                    const float bx = bias[col], by = bias[col + 1];
                    #pragma unroll
                    for (int half = 0; half < 2; half++) {
                        const int row = m0 + warp_m * 64 + mt * 16 + (lane >> 2) + half * 8;
                        const int bb = row >> 11, s = row & (SS - 1);
                        const int bhx = bb * HH + hh2;
                        float v0 = acc[mt][nt][half * 2 + 0] + bx;
                        float v1 = acc[mt][nt][half * 2 + 1] + by;
                        if (z == 0) { v0 *= qscale; v1 *= qscale; }
                        __nv_bfloat16 h0 = __float2bfloat16(v0);
                        __nv_bfloat16 h1 = __float2bfloat16(v1);
                        size_t off = ((size_t)bhx * SS + s) * DD + dd2;
                        __nv_bfloat16* dh = (z == 0) ? g_Qhi : g_Khi;
                        __nv_bfloat16* dl = (z == 0) ? g_Qlo : g_Klo;
                        __nv_bfloat162 ph; ph.x = h0; ph.y = h1;
                        __nv_bfloat162 pl;
                        pl.x = __float2bfloat16(v0 - __bfloat162float(h0));
                        pl.y = __float2bfloat16(v1 - __bfloat162float(h1));
                        *(__nv_bfloat162*)(dh + off) = ph;
                        *(__nv_bfloat162*)(dl + off) = pl;
                    }
                }
            }
        }
    } else {
        const float* bias = bias_all;
        #pragma unroll
        for (int mt = 0; mt < 4; mt++) {
            #pragma unroll
            for (int nt = 0; nt < 8; nt++) {
                const int col = n0 + warp_n * 64 + nt * 8 + (lane & 3) * 2;
                const float bx = bias[col], by = bias[col + 1];
                #pragma unroll
                for (int half = 0; half < 2; half++) {
                    const int row = m0 + warp_m * 64 + mt * 16 + (lane >> 2) + half * 8;
                    float2 o;
                    o.x = acc[mt][nt][half * 2 + 0] + bx;
                    o.y = acc[mt][nt][half * 2 + 1] + by;
                    *(float2*)(out1 + (size_t)row * EE + col) = o;
                }
            }
        }
    }
}

// ---------------- tensor-core flash attention, fixed-max softmax ----------------
#define AQ 128
#define AK 128
#define NKV (SS / AK)            // 16
#define A_OFF_Q    0             // Qhi 16KB, Qlo 16KB
#define A_BUF0     32768
#define A_OFF_KHI  0
#define A_OFF_KLO  16384
#define A_OFF_VHI  32768
#define A_OFF_VLO  49152
#define A_OFF_MB   65536
#define A_BUFSZ    67584         // 64K tiles + 2K mask
#define ATTN_SMEM  (A_BUF0 + 2 * A_BUFSZ)   // 167936
#define SOFTMAX_M  16.0f         // fixed log2-domain max; scores*log2e bounded ~|9|

__global__ __launch_bounds__(256) void attn_mma()
{
    extern __shared__ char smem[];
    const uint32_t sb = smem_u32(smem);
    const int tid = threadIdx.x;
    const int lane = tid & 31;
    const int warp = tid >> 5;

    const int q0 = blockIdx.x * AQ;
    const int h  = blockIdx.y;
    const int b  = blockIdx.z;
    const int bh = b * HH + h;

    const uint4* gQh = (const uint4*)(g_Qhi + (size_t)bh * SS * DD);
    const uint4* gQl = (const uint4*)(g_Qlo + (size_t)bh * SS * DD);
    const uint4* gKh = (const uint4*)(g_Khi + (size_t)bh * SS * DD);
    const uint4* gKl = (const uint4*)(g_Klo + (size_t)bh * SS * DD);
    const uint4* gVh = (const uint4*)(g_VThi + (size_t)bh * DD * SS);
    const uint4* gVl = (const uint4*)(g_VTlo + (size_t)bh * DD * SS);

    const int lr = tid >> 3;        // 0..31
    const int lj = tid & 7;         // 0..7
    const int vr = tid >> 4;        // 0..15
    const int vj = tid & 15;        // 0..15

    // issue Q
    {
        #pragma unroll
        for (int u = 0; u < 4; u++) {
            int r = lr + u * 32;
            uint32_t off = sw128((uint32_t)(r * 128 + lj * 16));
            cp_async16(sb + A_OFF_Q + off,          gQh + (size_t)(q0 + r) * 8 + lj);
            cp_async16(sb + A_OFF_Q + 16384 + off,  gQl + (size_t)(q0 + r) * 8 + lj);
        }
        cp_commit();
    }

    auto issue_tile = [&](int t) {
        if (t < NKV) {
            const int kv0 = t * AK;
            const uint32_t bbase = sb + A_BUF0 + (t & 1) * A_BUFSZ;
            #pragma unroll
            for (int u = 0; u < 4; u++) {
                int r = lr + u * 32;        // 0..127 (K rows)
                uint32_t off = sw128((uint32_t)(r * 128 + lj * 16));
                cp_async16(bbase + A_OFF_KHI + off, gKh + (size_t)(kv0 + r) * 8 + lj);
                cp_async16(bbase + A_OFF_KLO + off, gKl + (size_t)(kv0 + r) * 8 + lj);
            }
            #pragma unroll
            for (int u = 0; u < 4; u++) {
                int r = vr + u * 16;        // 0..63 (V d-rows)
                uint32_t off = sw256((uint32_t)(r * 256 + vj * 16));
                cp_async16(bbase + A_OFF_VHI + off, gVh + (size_t)r * 256 + kv0 / 8 + vj);
                cp_async16(bbase + A_OFF_VLO + off, gVl + (size_t)r * 256 + kv0 / 8 + vj);
            }
            if (tid < AQ)
                cp_async16(bbase + A_OFF_MB + tid * 16,
                           g_mb + (size_t)(q0 + tid) * (SS / 32) + kv0 / 32);
        }
        cp_commit();
    };

    issue_tile(0);

    const uint32_t ONE2 = 0x3F803F80u;   // bf16 {1.0, 1.0}

    uint32_t qh[4][4], ql[4][4];
    float lsum[4];                        // row-sum accumulator via MMA (cols identical)
    #pragma unroll
    for (int i = 0; i < 4; i++) lsum[i] = 0.f;
    float acc[8][4];
    #pragma unroll
    for (int nt = 0; nt < 8; nt++)
        #pragma unroll
        for (int i = 0; i < 4; i++) acc[nt][i] = 0.f;

    for (int t = 0; t < NKV; t++) {
        issue_tile(t + 1);
        cp_wait<1>();
        __syncthreads();

        if (t == 0) {
            #pragma unroll
            for (int kk = 0; kk < 4; kk++) {
                int row = warp * 16 + (lane & 15);
                int ch  = kk * 2 + (lane >> 4);
                uint32_t off = sw128((uint32_t)(row * 128 + ch * 16));
                ldsm_x4(sb + A_OFF_Q + off,         qh[kk][0], qh[kk][1], qh[kk][2], qh[kk][3]);
                ldsm_x4(sb + A_OFF_Q + 16384 + off, ql[kk][0], ql[kk][1], ql[kk][2], ql[kk][3]);
            }
        }

        const uint32_t bbase = sb + A_BUF0 + (t & 1) * A_BUFSZ;

        // ---- scores: S[128 x 128] hi/lo 3-pass (already in log2 domain) ----
        float s[16][4];
        #pragma unroll
        for (int nt = 0; nt < 16; nt++)
            #pragma unroll
            for (int i = 0; i < 4; i++) s[nt][i] = 0.f;

        #pragma unroll
        for (int kk = 0; kk < 4; kk++) {
            #pragma unroll
            for (int p = 0; p < 8; p++) {
                int nr = p * 16 + ((lane & 7) | ((lane & 16) >> 1));
                int ch = kk * 2 + ((lane >> 3) & 1);
                uint32_t off = sw128((uint32_t)(nr * 128 + ch * 16));
                uint32_t bh4[4], bl4[4];
                ldsm_x4(bbase + A_OFF_KHI + off, bh4[0], bh4[1], bh4[2], bh4[3]);
                ldsm_x4(bbase + A_OFF_KLO + off, bl4[0], bl4[1], bl4[2], bl4[3]);
                #pragma unroll
                for (int half = 0; half < 2; half++) {
                    const int nt = p * 2 + half;
                    mma16816(s[nt], qh[kk], bh4[half * 2], bh4[half * 2 + 1]);
                    mma16816(s[nt], qh[kk], bl4[half * 2], bl4[half * 2 + 1]);
                    mma16816(s[nt], ql[kk], bh4[half * 2], bh4[half * 2 + 1]);
                }
            }
        }

        // ---- mask + fixed-max exp: p = mask ? 2^(s - M) : 0 ----
        uint32_t mw[2][4];
        #pragma unroll
        for (int hf = 0; hf < 2; hf++) {
            int row = warp * 16 + (lane >> 2) + hf * 8;
            uint4 m4 = *(const uint4*)(smem + (A_BUF0 + (t & 1) * A_BUFSZ + A_OFF_MB) + row * 16);
            mw[hf][0] = m4.x; mw[hf][1] = m4.y; mw[hf][2] = m4.z; mw[hf][3] = m4.w;
        }
        #pragma unroll
        for (int nt = 0; nt < 16; nt++) {
            int w = nt >> 2;
            int bp0 = ((nt & 3) << 3) + 2 * (lane & 3);
            float p0 = exp2f(s[nt][0] - SOFTMAX_M);
            float p1 = exp2f(s[nt][1] - SOFTMAX_M);
            float p2 = exp2f(s[nt][2] - SOFTMAX_M);
            float p3 = exp2f(s[nt][3] - SOFTMAX_M);
            s[nt][0] = ((mw[0][w] >> bp0) & 1)       ? p0 : 0.f;
            s[nt][1] = ((mw[0][w] >> (bp0 + 1)) & 1) ? p1 : 0.f;
            s[nt][2] = ((mw[1][w] >> bp0) & 1)       ? p2 : 0.f;
            s[nt][3] = ((mw[1][w] >> (bp0 + 1)) & 1) ? p3 : 0.f;
        }

        // ---- PV + row-sum: acc += P*V (3-pass); lsum += P*ones ----
        #pragma unroll
        for (int kk = 0; kk < 8; kk++) {
            uint32_t ah4[4], al4[4];
            #pragma unroll
            for (int q2 = 0; q2 < 4; q2++) {
                const int nt = 2 * kk + (q2 >> 1);
                const int i0 = (q2 & 1) * 2;
                float p0 = s[nt][i0], p1 = s[nt][i0 + 1];
                __nv_bfloat162 hp = __floats2bfloat162_rn(p0, p1);
                float r0 = p0 - __bfloat162float(hp.x);
                float r1 = p1 - __bfloat162float(hp.y);
                __nv_bfloat162 lp = __floats2bfloat162_rn(r0, r1);
                ah4[q2] = *(uint32_t*)&hp;
                al4[q2] = *(uint32_t*)&lp;
            }
            // row sums of P (hi+lo) via MMA against ones
            mma16816(lsum, ah4, ONE2, ONE2);
            mma16816(lsum, al4, ONE2, ONE2);
            #pragma unroll
            for (int p = 0; p < 4; p++) {
                int nr = p * 16 + ((lane & 7) | ((lane & 16) >> 1));
                int ch = kk * 2 + ((lane >> 3) & 1);
                uint32_t off = sw256((uint32_t)(nr * 256 + ch * 16));
                uint32_t vh4[4], vl4[4];
                ldsm_x4(bbase + A_OFF_VHI + off, vh4[0], vh4[1], vh4[2], vh4[3]);
                ldsm_x4(bbase + A_OFF_VLO + off, vl4[0], vl4[1], vl4[2], vl4[3]);
                #pragma unroll
                for (int half = 0; half < 2; half++) {
                    const int nt2 = p * 2 + half;
                    mma16816(acc[nt2], ah4, vh4[half * 2], vh4[half * 2 + 1]);
                    mma16816(acc[nt2], ah4, vl4[half * 2], vl4[half * 2 + 1]);
                    mma16816(acc[nt2], al4, vh4[half * 2], vh4[half * 2 + 1]);
                }
            }
        }
        __syncthreads();
    }

    // ---- epilogue: normalize by MMA-accumulated row sums ----
    float inv[2];
    inv[0] = 1.f / lsum[0];
    inv[1] = 1.f / lsum[2];
    #pragma unroll
    for (int nt = 0; nt < 8; nt++) {
        const int d = nt * 8 + (lane & 3) * 2;
        #pragma unroll
        for (int hf = 0; hf < 2; hf++) {
            const int row = q0 + warp * 16 + (lane >> 2) + hf * 8;
            float v0 = acc[nt][hf * 2 + 0] * inv[hf];
            float v1 = acc[nt][hf * 2 + 1] * inv[hf];
            __nv_bfloat16 h0 = __float2bfloat16(v0);
            __nv_bfloat16 h1 = __float2bfloat16(v1);
            __nv_bfloat162 ph; ph.x = h0; ph.y = h1;
            __nv_bfloat162 pl;
            pl.x = __float2bfloat16(v0 - __bfloat162float(h0));
            pl.y = __float2bfloat16(v1 - __bfloat162float(h1));
            size_t off = ((size_t)(b * SS + row)) * EE + h * DD + d;
            *(__nv_bfloat162*)(g_Chi + off) = ph;
            *(__nv_bfloat162*)(g_Clo + off) = pl;
        }
    }
}

// ---------------- launch ----------------
extern "C" void kernel_launch(void* const* d_in, const int* in_sizes, int n_in,
                              void* d_out, int out_size)
{
    const float* q    = (const float*)d_in[0];
    const float* k    = (const float*)d_in[1];
    const float* v    = (const float*)d_in[2];
    const int*   mask = (const int*)  d_in[3];
    const float* Wqkv = (const float*)d_in[4];
    const float* bqkv = (const float*)d_in[5];
    const float* Wout = (const float*)d_in[6];
    const float* bout = (const float*)d_in[7];
    float* out = (float*)d_out;

    cudaFuncSetAttribute(mma_gemm<0>, cudaFuncAttributeMaxDynamicSharedMemorySize, GEMM_SMEM);
    cudaFuncSetAttribute(mma_gemm<1>, cudaFuncAttributeMaxDynamicSharedMemorySize, GEMM_SMEM);
    cudaFuncSetAttribute(attn_mma,    cudaFuncAttributeMaxDynamicSharedMemorySize, ATTN_SMEM);

    __nv_bfloat16 *Ahi, *Alo, *Whi, *Wlo, *Chi, *Clo;
    cudaGetSymbolAddress((void**)&Ahi, g_Ahi);
    cudaGetSymbolAddress((void**)&Alo, g_Alo);
    cudaGetSymbolAddress((void**)&Whi, g_Whi);
    cudaGetSymbolAddress((void**)&Wlo, g_Wlo);
    cudaGetSymbolAddress((void**)&Chi, g_Chi);
    cudaGetSymbolAddress((void**)&Clo, g_Clo);

    const int n4 = MT * EE / 4;
    conv_rows3<<<dim3(n4 / 256, 3), 256>>>(q, k, v, Ahi, Alo);

    conv_wT<<<dim3(3 * EE / 32, EE / 32), 256>>>(Wqkv, 3 * EE, Whi, Wlo);
    conv_wT<<<dim3(EE / 32, EE / 32), 256>>>(Wout, EE, Whi + (size_t)3 * EE * EE, Wlo + (size_t)3 * EE * EE);

    mask_bits<<<SS * SS / 1024, 256>>>(mask);

    mma_gemm<0><<<dim3(EE / 128, MT / Bb, 3), 256, GEMM_SMEM>>>(Ahi, Alo, bqkv, nullptr);

    attn_mma<<<dim3(SS / AQ, HH, BB), 256, ATTN_SMEM>>>();

    mma_gemm<1><<<dim3(EE / 128, MT / Bb, 1), 256, GEMM_SMEM>>>(Chi, Clo, bout, out);
}

// round 13
// speedup vs baseline: 1.5495x; 1.5495x over previous
#include <cuda_runtime.h>
#include <cuda_bf16.h>
#include <cstdint>
#include <math.h>

#define BB 2
#define SS 2048
#define EE 1024
#define HH 16
#define DD 64
#define MT 4096          // rows per GEMM (B*S)

// ---------------- scratch (__device__ globals; no allocs allowed) ----------------
__device__ __nv_bfloat16 g_Ahi[3*MT*EE];     // q,k,v activations hi
__device__ __nv_bfloat16 g_Alo[3*MT*EE];     // residual lo
__device__ __nv_bfloat16 g_Whi[4*EE*EE];     // W^T rows: [0,3072)=qkv, [3072,4096)=out
__device__ __nv_bfloat16 g_Wlo[4*EE*EE];

__device__ __nv_bfloat16 g_Qhi[BB*HH*SS*DD]; // pre-scaled by 0.125*log2(e), [b,h][s][d]
__device__ __nv_bfloat16 g_Qlo[BB*HH*SS*DD];
__device__ __nv_bfloat16 g_Khi[BB*HH*SS*DD]; // [b,h][s][d]
__device__ __nv_bfloat16 g_Klo[BB*HH*SS*DD];
__device__ __nv_bfloat16 g_VThi[BB*HH*DD*SS]; // transposed: [b,h][d][s]
__device__ __nv_bfloat16 g_VTlo[BB*HH*DD*SS];

__device__ __nv_bfloat16 g_Chi[MT*EE];       // ctx hi   [b,s][e]
__device__ __nv_bfloat16 g_Clo[MT*EE];
__device__ uint32_t g_mb[SS*(SS/32)];        // mask bits [q][kword]

// ---------------- helpers ----------------
__device__ __forceinline__ uint32_t smem_u32(const void* p) {
    uint32_t a;
    asm("{ .reg .u64 t; cvta.to.shared.u64 t, %1; cvt.u32.u64 %0, t; }" : "=r"(a) : "l"(p));
    return a;
}
__device__ __forceinline__ uint32_t sw128(uint32_t off) { return off ^ ((off >> 3) & 0x70); }
__device__ __forceinline__ uint32_t sw256(uint32_t off) { return off ^ ((off >> 4) & 0x70); }

__device__ __forceinline__ float ex2_fast(float x) {
    float r;
    asm("ex2.approx.ftz.f32 %0, %1;" : "=f"(r) : "f"(x));
    return r;
}

__device__ __forceinline__ void cp_async16(uint32_t dst, const void* src) {
    asm volatile("cp.async.cg.shared.global [%0], [%1], 16;" :: "r"(dst), "l"(src) : "memory");
}
__device__ __forceinline__ void cp_commit() {
    asm volatile("cp.async.commit_group;" ::: "memory");
}
template <int N> __device__ __forceinline__ void cp_wait() {
    asm volatile("cp.async.wait_group %0;" :: "n"(N) : "memory");
}
__device__ __forceinline__ void ldsm_x4(uint32_t addr, uint32_t& r0, uint32_t& r1, uint32_t& r2, uint32_t& r3) {
    asm volatile("ldmatrix.sync.aligned.m8n8.x4.shared.b16 {%0,%1,%2,%3}, [%4];"
        : "=r"(r0), "=r"(r1), "=r"(r2), "=r"(r3) : "r"(addr));
}
__device__ __forceinline__ void mma16816(float* c, const uint32_t* a, uint32_t b0, uint32_t b1) {
    asm volatile("mma.sync.aligned.m16n8k16.row.col.f32.bf16.bf16.f32 "
        "{%0,%1,%2,%3}, {%4,%5,%6,%7}, {%8,%9}, {%0,%1,%2,%3};"
        : "+f"(c[0]), "+f"(c[1]), "+f"(c[2]), "+f"(c[3])
        : "r"(a[0]), "r"(a[1]), "r"(a[2]), "r"(a[3]), "r"(b0), "r"(b1));
}

// ---------------- conversion kernels ----------------
__global__ __launch_bounds__(256) void conv_rows3(
    const float* __restrict__ q, const float* __restrict__ k, const float* __restrict__ v,
    __nv_bfloat16* __restrict__ dhi, __nv_bfloat16* __restrict__ dlo)
{
    const int z = blockIdx.y;
    const float* src = (z == 0) ? q : (z == 1) ? k : v;
    size_t base = (size_t)z * MT * EE;
    int idx = blockIdx.x * 256 + threadIdx.x;
    float4 x = ((const float4*)src)[idx];
    __nv_bfloat16 hh[4], ll[4];
    float xs[4] = {x.x, x.y, x.z, x.w};
    #pragma unroll
    for (int i = 0; i < 4; i++) {
        hh[i] = __float2bfloat16(xs[i]);
        ll[i] = __float2bfloat16(xs[i] - __bfloat162float(hh[i]));
    }
    *(uint2*)&dhi[base + (size_t)idx * 4] = *(uint2*)hh;
    *(uint2*)&dlo[base + (size_t)idx * 4] = *(uint2*)ll;
}

__global__ __launch_bounds__(256) void conv_wT(
    const float* __restrict__ W, int ldn,
    __nv_bfloat16* __restrict__ dhi, __nv_bfloat16* __restrict__ dlo)
{
    __shared__ float t[32][33];
    const int n0 = blockIdx.x * 32;
    const int k0 = blockIdx.y * 32;
    const int tid = threadIdx.x;
    {
        int tx = tid & 31, ty = tid >> 5;
        #pragma unroll
        for (int r = 0; r < 4; r++) {
            int k = ty + r * 8;
            t[tx][k] = W[(size_t)(k0 + k) * ldn + n0 + tx];
        }
    }
    __syncthreads();
    {
        int tkg = tid & 7, tn = tid >> 3;
        __nv_bfloat16 hh[4], ll[4];
        #pragma unroll
        for (int i = 0; i < 4; i++) {
            float v = t[tn][tkg * 4 + i];
            hh[i] = __float2bfloat16(v);
            ll[i] = __float2bfloat16(v - __bfloat162float(hh[i]));
        }
        size_t off = (size_t)(n0 + tn) * EE + k0 + tkg * 4;
        *(uint2*)&dhi[off] = *(uint2*)hh;
        *(uint2*)&dlo[off] = *(uint2*)ll;
    }
}

// mask [S][S] int32 -> bit words. int4 loads, nibble pack in smem.
__global__ __launch_bounds__(256) void mask_bits(const int* __restrict__ mask)
{
    __shared__ unsigned char sn[256];
    int t = blockIdx.x * 256 + threadIdx.x;
    int4 x = ((const int4*)mask)[t];
    unsigned nib = (unsigned)(x.x != 0) | ((unsigned)(x.y != 0) << 1)
                 | ((unsigned)(x.z != 0) << 2) | ((unsigned)(x.w != 0) << 3);
    sn[threadIdx.x] = (unsigned char)nib;
    __syncthreads();
    if (threadIdx.x < 32) {
        unsigned w = 0;
        #pragma unroll
        for (int k = 0; k < 8; k++)
            w |= (unsigned)sn[threadIdx.x * 8 + k] << (4 * k);
        g_mb[blockIdx.x * 32 + threadIdx.x] = w;
    }
}

// ---------------- HMMA GEMM, 256x128 tile, 2-stage ----------------
#define Bb 256               // M tile
#define TILE_A 32768         // 256 rows x 128B
#define TILE_W 16384         // 128 rows x 128B
#define BUF_B  (2 * TILE_A + 2 * TILE_W)   // 98304
#define GEMM_SMEM (2 * BUF_B)              // 196608
#define NCHUNK 16

template <int MODE>
__global__ __launch_bounds__(256, 1) void mma_gemm(
    const __nv_bfloat16* __restrict__ Ahi, const __nv_bfloat16* __restrict__ Alo,
    const float* __restrict__ bias_all, float* __restrict__ out1)
{
    extern __shared__ char smem[];
    const uint32_t sb = smem_u32(smem);
    const int tid = threadIdx.x;
    const int wid = tid >> 5;
    const int lane = tid & 31;
    const int warp_m = wid & 3;      // 4 warps over 256 rows (64 each)
    const int warp_n = wid >> 2;     // 2 warps over 128 cols (64 each)

    const int n0 = blockIdx.x * 128;
    const int m0 = blockIdx.y * Bb;
    int z = 0, wbase;
    if (MODE == 0) { z = blockIdx.z; wbase = z * EE; } else { wbase = 3 * EE; }

    const uint4* gA0 = (const uint4*)(Ahi + ((MODE == 0) ? (size_t)z * MT * EE : 0) + (size_t)m0 * EE);
    const uint4* gA1 = (const uint4*)(Alo + ((MODE == 0) ? (size_t)z * MT * EE : 0) + (size_t)m0 * EE);
    const uint4* gB0 = (const uint4*)(g_Whi + (size_t)(wbase + n0) * EE);
    const uint4* gB1 = (const uint4*)(g_Wlo + (size_t)(wbase + n0) * EE);

    float acc[4][8][4];
    #pragma unroll
    for (int mt = 0; mt < 4; mt++)
        #pragma unroll
        for (int nt = 0; nt < 8; nt++)
            #pragma unroll
            for (int i = 0; i < 4; i++) acc[mt][nt][i] = 0.f;

    const int lr = tid >> 3;   // 0..31
    const int lj = tid & 7;    // 0..7

    auto load_chunk = [&](int c) {
        const uint32_t bbase = sb + (c & 1) * BUF_B;
        #pragma unroll
        for (int u = 0; u < 8; u++) {
            int r = lr + u * 32;
            uint32_t off = sw128((uint32_t)(r * 128 + lj * 16));
            cp_async16(bbase + 0 * TILE_A + off, gA0 + (size_t)r * 128 + c * 8 + lj);
            cp_async16(bbase + 1 * TILE_A + off, gA1 + (size_t)r * 128 + c * 8 + lj);
        }
        #pragma unroll
        for (int u = 0; u < 4; u++) {
            int r = lr + u * 32;
            uint32_t off = sw128((uint32_t)(r * 128 + lj * 16));
            cp_async16(bbase + 2 * TILE_A + 0 * TILE_W + off, gB0 + (size_t)r * 128 + c * 8 + lj);
            cp_async16(bbase + 2 * TILE_A + 1 * TILE_W + off, gB1 + (size_t)r * 128 + c * 8 + lj);
        }
        cp_commit();
    };

    load_chunk(0);

    for (int c = 0; c < NCHUNK; c++) {
        if (c + 1 < NCHUNK) { load_chunk(c + 1); cp_wait<1>(); }
        else                { cp_wait<0>(); }
        __syncthreads();

        const uint32_t bbase = sb + (c & 1) * BUF_B;
        #pragma unroll
        for (int kk = 0; kk < 4; kk++) {
            uint32_t ah[4][4], al2[4][4];
            #pragma unroll
            for (int mt = 0; mt < 4; mt++) {
                int row = warp_m * 64 + mt * 16 + (lane & 15);
                int ch  = kk * 2 + (lane >> 4);
                uint32_t off = sw128((uint32_t)(row * 128 + ch * 16));
                ldsm_x4(bbase + 0 * TILE_A + off, ah[mt][0], ah[mt][1], ah[mt][2], ah[mt][3]);
                ldsm_x4(bbase + 1 * TILE_A + off, al2[mt][0], al2[mt][1], al2[mt][2], al2[mt][3]);
            }
            #pragma unroll
            for (int p = 0; p < 4; p++) {
                int nr = warp_n * 64 + p * 16 + ((lane & 7) | ((lane & 16) >> 1));
                int ch = kk * 2 + ((lane >> 3) & 1);
                uint32_t off = sw128((uint32_t)(nr * 128 + ch * 16));
                uint32_t bh4[4], bl4[4];
                ldsm_x4(bbase + 2 * TILE_A + 0 * TILE_W + off, bh4[0], bh4[1], bh4[2], bh4[3]);
                ldsm_x4(bbase + 2 * TILE_A + 1 * TILE_W + off, bl4[0], bl4[1], bl4[2], bl4[3]);
                #pragma unroll
                for (int mt = 0; mt < 4; mt++) {
                    #pragma unroll
                    for (int half = 0; half < 2; half++) {
                        const int nt = p * 2 + half;
                        mma16816(acc[mt][nt], ah[mt],  bh4[half * 2], bh4[half * 2 + 1]);
                        mma16816(acc[mt][nt], ah[mt],  bl4[half * 2], bl4[half * 2 + 1]);
                        mma16816(acc[mt][nt], al2[mt], bh4[half * 2], bh4[half * 2 + 1]);
                    }
                }
            }
        }
        __syncthreads();
    }

    // ---------------- epilogue ----------------
    if (MODE == 0) {
        const float* bias = bias_all + z * EE;
        if (z == 2) {
            // stage through smem (f32), write VT coalesced
            float* st = (float*)smem;
            const int STR = 264;
            #pragma unroll
            for (int mt = 0; mt < 4; mt++) {
                #pragma unroll
                for (int nt = 0; nt < 8; nt++) {
                    const int col_l = warp_n * 64 + nt * 8 + (lane & 3) * 2;
                    const float bx = bias[n0 + col_l], by = bias[n0 + col_l + 1];
                    #pragma unroll
                    for (int half = 0; half < 2; half++) {
                        const int row_l = warp_m * 64 + mt * 16 + (lane >> 2) + half * 8;
                        st[col_l * STR + row_l]       = acc[mt][nt][half * 2 + 0] + bx;
                        st[(col_l + 1) * STR + row_l] = acc[mt][nt][half * 2 + 1] + by;
                    }
                }
            }
            __syncthreads();
            const int nl = tid >> 1;
            const int mh = (tid & 1) * 128;
            const int col = n0 + nl;
            const int h = col >> 6, d = col & 63;
            const int row0g = m0 + mh;
            const int bbv = row0g >> 11, s0 = row0g & (SS - 1);
            size_t base = ((size_t)(bbv * HH + h) * DD + d) * SS + s0;
            const float* srow = st + nl * STR + mh;
            #pragma unroll
            for (int i = 0; i < 128; i += 4) {
                float4 xv = *(const float4*)(srow + i);
                __nv_bfloat16 h4[4], l4[4];
                float xs[4] = {xv.x, xv.y, xv.z, xv.w};
                #pragma unroll
                for (int j = 0; j < 4; j++) {
                    h4[j] = __float2bfloat16(xs[j]);
                    l4[j] = __float2bfloat16(xs[j] - __bfloat162float(h4[j]));
                }
                *(uint2*)(g_VThi + base + i) = *(uint2*)h4;
                *(uint2*)(g_VTlo + base + i) = *(uint2*)l4;
            }
        } else {
            // Q pre-scale folds 1/sqrt(D) AND log2(e) so attention uses exp2 directly.
            const float qscale = 0.125f * 1.44269504f;
            #pragma unroll
            for (int mt = 0; mt < 4; mt++) {
                #pragma unroll
                for (int nt = 0; nt < 8; nt++) {
                    const int col = n0 + warp_n * 64 + nt * 8 + (lane & 3) * 2;
                    const int hh2 = col >> 6, dd2 = col & 63;
                    const float bx = bias[col], by = bias[col + 1];
                    #pragma unroll
                    for (int half = 0; half < 2; half++) {
                        const int row = m0 + warp_m * 64 + mt * 16 + (lane >> 2) + half * 8;
                        const int bb = row >> 11, s = row & (SS - 1);
                        const int bhx = bb * HH + hh2;
                        float v0 = acc[mt][nt][half * 2 + 0] + bx;
                        float v1 = acc[mt][nt][half * 2 + 1] + by;
                        if (z == 0) { v0 *= qscale; v1 *= qscale; }
                        __nv_bfloat16 h0 = __float2bfloat16(v0);
                        __nv_bfloat16 h1 = __float2bfloat16(v1);
                        size_t off = ((size_t)bhx * SS + s) * DD + dd2;
                        __nv_bfloat16* dh = (z == 0) ? g_Qhi : g_Khi;
                        __nv_bfloat16* dl = (z == 0) ? g_Qlo : g_Klo;
                        __nv_bfloat162 ph; ph.x = h0; ph.y = h1;
                        __nv_bfloat162 pl;
                        pl.x = __float2bfloat16(v0 - __bfloat162float(h0));
                        pl.y = __float2bfloat16(v1 - __bfloat162float(h1));
                        *(__nv_bfloat162*)(dh + off) = ph;
                        *(__nv_bfloat162*)(dl + off) = pl;
                    }
                }
            }
        }
    } else {
        const float* bias = bias_all;
        #pragma unroll
        for (int mt = 0; mt < 4; mt++) {
            #pragma unroll
            for (int nt = 0; nt < 8; nt++) {
                const int col = n0 + warp_n * 64 + nt * 8 + (lane & 3) * 2;
                const float bx = bias[col], by = bias[col + 1];
                #pragma unroll
                for (int half = 0; half < 2; half++) {
                    const int row = m0 + warp_m * 64 + mt * 16 + (lane >> 2) + half * 8;
                    float2 o;
                    o.x = acc[mt][nt][half * 2 + 0] + bx;
                    o.y = acc[mt][nt][half * 2 + 1] + by;
                    *(float2*)(out1 + (size_t)row * EE + col) = o;
                }
            }
        }
    }
}

// ---------------- tensor-core flash attention, fixed-max softmax ----------------
#define AQ 128
#define AK 128
#define NKV (SS / AK)            // 16
#define A_OFF_Q    0             // Qhi 16KB, Qlo 16KB
#define A_BUF0     32768
#define A_OFF_KHI  0
#define A_OFF_KLO  16384
#define A_OFF_VHI  32768
#define A_OFF_VLO  49152
#define A_OFF_MB   65536
#define A_BUFSZ    67584         // 64K tiles + 2K mask
#define ATTN_SMEM  (A_BUF0 + 2 * A_BUFSZ)   // 167936
#define SOFTMAX_M  16.0f         // fixed log2-domain max; scores*log2e bounded ~|9|

__global__ __launch_bounds__(256) void attn_mma()
{
    extern __shared__ char smem[];
    const uint32_t sb = smem_u32(smem);
    const int tid = threadIdx.x;
    const int lane = tid & 31;
    const int warp = tid >> 5;

    const int q0 = blockIdx.x * AQ;
    const int h  = blockIdx.y;
    const int b  = blockIdx.z;
    const int bh = b * HH + h;

    const uint4* gQh = (const uint4*)(g_Qhi + (size_t)bh * SS * DD);
    const uint4* gQl = (const uint4*)(g_Qlo + (size_t)bh * SS * DD);
    const uint4* gKh = (const uint4*)(g_Khi + (size_t)bh * SS * DD);
    const uint4* gKl = (const uint4*)(g_Klo + (size_t)bh * SS * DD);
    const uint4* gVh = (const uint4*)(g_VThi + (size_t)bh * DD * SS);
    const uint4* gVl = (const uint4*)(g_VTlo + (size_t)bh * DD * SS);

    const int lr = tid >> 3;        // 0..31
    const int lj = tid & 7;         // 0..7
    const int vr = tid >> 4;        // 0..15
    const int vj = tid & 15;        // 0..15

    // issue Q
    {
        #pragma unroll
        for (int u = 0; u < 4; u++) {
            int r = lr + u * 32;
            uint32_t off = sw128((uint32_t)(r * 128 + lj * 16));
            cp_async16(sb + A_OFF_Q + off,          gQh + (size_t)(q0 + r) * 8 + lj);
            cp_async16(sb + A_OFF_Q + 16384 + off,  gQl + (size_t)(q0 + r) * 8 + lj);
        }
        cp_commit();
    }

    auto issue_tile = [&](int t) {
        if (t < NKV) {
            const int kv0 = t * AK;
            const uint32_t bbase = sb + A_BUF0 + (t & 1) * A_BUFSZ;
            #pragma unroll
            for (int u = 0; u < 4; u++) {
                int r = lr + u * 32;        // 0..127 (K rows)
                uint32_t off = sw128((uint32_t)(r * 128 + lj * 16));
                cp_async16(bbase + A_OFF_KHI + off, gKh + (size_t)(kv0 + r) * 8 + lj);
                cp_async16(bbase + A_OFF_KLO + off, gKl + (size_t)(kv0 + r) * 8 + lj);
            }
            #pragma unroll
            for (int u = 0; u < 4; u++) {
                int r = vr + u * 16;        // 0..63 (V d-rows)
                uint32_t off = sw256((uint32_t)(r * 256 + vj * 16));
                cp_async16(bbase + A_OFF_VHI + off, gVh + (size_t)r * 256 + kv0 / 8 + vj);
                cp_async16(bbase + A_OFF_VLO + off, gVl + (size_t)r * 256 + kv0 / 8 + vj);
            }
            if (tid < AQ)
                cp_async16(bbase + A_OFF_MB + tid * 16,
                           g_mb + (size_t)(q0 + tid) * (SS / 32) + kv0 / 32);
        }
        cp_commit();
    };

    issue_tile(0);

    const uint32_t ONE2 = 0x3F803F80u;   // bf16 {1.0, 1.0}

    uint32_t qh[4][4], ql[4][4];
    float lsum[4];                        // row-sum accumulator via MMA
    #pragma unroll
    for (int i = 0; i < 4; i++) lsum[i] = 0.f;
    float acc[8][4];
    #pragma unroll
    for (int nt = 0; nt < 8; nt++)
        #pragma unroll
        for (int i = 0; i < 4; i++) acc[nt][i] = 0.f;

    for (int t = 0; t < NKV; t++) {
        issue_tile(t + 1);
        cp_wait<1>();
        __syncthreads();

        if (t == 0) {
            #pragma unroll
            for (int kk = 0; kk < 4; kk++) {
                int row = warp * 16 + (lane & 15);
                int ch  = kk * 2 + (lane >> 4);
                uint32_t off = sw128((uint32_t)(row * 128 + ch * 16));
                ldsm_x4(sb + A_OFF_Q + off,         qh[kk][0], qh[kk][1], qh[kk][2], qh[kk][3]);
                ldsm_x4(sb + A_OFF_Q + 16384 + off, ql[kk][0], ql[kk][1], ql[kk][2], ql[kk][3]);
            }
        }

        const uint32_t bbase = sb + A_BUF0 + (t & 1) * A_BUFSZ;

        // ---- scores: S[128 x 128] hi/lo 3-pass (log2 domain) ----
        float s[16][4];
        #pragma unroll
        for (int nt = 0; nt < 16; nt++)
            #pragma unroll
            for (int i = 0; i < 4; i++) s[nt][i] = 0.f;

        #pragma unroll
        for (int kk = 0; kk < 4; kk++) {
            #pragma unroll
            for (int p = 0; p < 8; p++) {
                int nr = p * 16 + ((lane & 7) | ((lane & 16) >> 1));
                int ch = kk * 2 + ((lane >> 3) & 1);
                uint32_t off = sw128((uint32_t)(nr * 128 + ch * 16));
                uint32_t bh4[4], bl4[4];
                ldsm_x4(bbase + A_OFF_KHI + off, bh4[0], bh4[1], bh4[2], bh4[3]);
                ldsm_x4(bbase + A_OFF_KLO + off, bl4[0], bl4[1], bl4[2], bl4[3]);
                #pragma unroll
                for (int half = 0; half < 2; half++) {
                    const int nt = p * 2 + half;
                    mma16816(s[nt], qh[kk], bh4[half * 2], bh4[half * 2 + 1]);
                    mma16816(s[nt], qh[kk], bl4[half * 2], bl4[half * 2 + 1]);
                    mma16816(s[nt], ql[kk], bh4[half * 2], bh4[half * 2 + 1]);
                }
            }
        }

        // ---- mask + fixed-max exp: p = mask ? 2^(s - M) : 0  (MUFU.EX2) ----
        uint32_t mw[2][4];
        #pragma unroll
        for (int hf = 0; hf < 2; hf++) {
            int row = warp * 16 + (lane >> 2) + hf * 8;
            uint4 m4 = *(const uint4*)(smem + (A_BUF0 + (t & 1) * A_BUFSZ + A_OFF_MB) + row * 16);
            mw[hf][0] = m4.x; mw[hf][1] = m4.y; mw[hf][2] = m4.z; mw[hf][3] = m4.w;
        }
        #pragma unroll
        for (int nt = 0; nt < 16; nt++) {
            int w = nt >> 2;
            int bp0 = ((nt & 3) << 3) + 2 * (lane & 3);
            float p0 = ex2_fast(s[nt][0] - SOFTMAX_M);
            float p1 = ex2_fast(s[nt][1] - SOFTMAX_M);
            float p2 = ex2_fast(s[nt][2] - SOFTMAX_M);
            float p3 = ex2_fast(s[nt][3] - SOFTMAX_M);
            s[nt][0] = ((mw[0][w] >> bp0) & 1)       ? p0 : 0.f;
            s[nt][1] = ((mw[0][w] >> (bp0 + 1)) & 1) ? p1 : 0.f;
            s[nt][2] = ((mw[1][w] >> bp0) & 1)       ? p2 : 0.f;
            s[nt][3] = ((mw[1][w] >> (bp0 + 1)) & 1) ? p3 : 0.f;
        }

        // ---- PV + row-sum: acc += P*V (3-pass); lsum += P*ones ----
        #pragma unroll
        for (int kk = 0; kk < 8; kk++) {
            uint32_t ah4[4], al4[4];
            #pragma unroll
            for (int q2 = 0; q2 < 4; q2++) {
                const int nt = 2 * kk + (q2 >> 1);
                const int i0 = (q2 & 1) * 2;
                float p0 = s[nt][i0], p1 = s[nt][i0 + 1];
                __nv_bfloat162 hp = __floats2bfloat162_rn(p0, p1);
                float r0 = p0 - __bfloat162float(hp.x);
                float r1 = p1 - __bfloat162float(hp.y);
                __nv_bfloat162 lp = __floats2bfloat162_rn(r0, r1);
                ah4[q2] = *(uint32_t*)&hp;
                al4[q2] = *(uint32_t*)&lp;
            }
            mma16816(lsum, ah4, ONE2, ONE2);
            mma16816(lsum, al4, ONE2, ONE2);
            #pragma unroll
            for (int p = 0; p < 4; p++) {
                int nr = p * 16 + ((lane & 7) | ((lane & 16) >> 1));
                int ch = kk * 2 + ((lane >> 3) & 1);
                uint32_t off = sw256((uint32_t)(nr * 256 + ch * 16));
                uint32_t vh4[4], vl4[4];
                ldsm_x4(bbase + A_OFF_VHI + off, vh4[0], vh4[1], vh4[2], vh4[3]);
                ldsm_x4(bbase + A_OFF_VLO + off, vl4[0], vl4[1], vl4[2], vl4[3]);
                #pragma unroll
                for (int half = 0; half < 2; half++) {
                    const int nt2 = p * 2 + half;
                    mma16816(acc[nt2], ah4, vh4[half * 2], vh4[half * 2 + 1]);
                    mma16816(acc[nt2], ah4, vl4[half * 2], vl4[half * 2 + 1]);
                    mma16816(acc[nt2], al4, vh4[half * 2], vh4[half * 2 + 1]);
                }
            }
        }
        __syncthreads();
    }

    // ---- epilogue: normalize by MMA-accumulated row sums ----
    float inv[2];
    inv[0] = 1.f / lsum[0];
    inv[1] = 1.f / lsum[2];
    #pragma unroll
    for (int nt = 0; nt < 8; nt++) {
        const int d = nt * 8 + (lane & 3) * 2;
        #pragma unroll
        for (int hf = 0; hf < 2; hf++) {
            const int row = q0 + warp * 16 + (lane >> 2) + hf * 8;
            float v0 = acc[nt][hf * 2 + 0] * inv[hf];
            float v1 = acc[nt][hf * 2 + 1] * inv[hf];
            __nv_bfloat16 h0 = __float2bfloat16(v0);
            __nv_bfloat16 h1 = __float2bfloat16(v1);
            __nv_bfloat162 ph; ph.x = h0; ph.y = h1;
            __nv_bfloat162 pl;
            pl.x = __float2bfloat16(v0 - __bfloat162float(h0));
            pl.y = __float2bfloat16(v1 - __bfloat162float(h1));
            size_t off = ((size_t)(b * SS + row)) * EE + h * DD + d;
            *(__nv_bfloat162*)(g_Chi + off) = ph;
            *(__nv_bfloat162*)(g_Clo + off) = pl;
        }
    }
}

// ---------------- launch ----------------
extern "C" void kernel_launch(void* const* d_in, const int* in_sizes, int n_in,
                              void* d_out, int out_size)
{
    const float* q    = (const float*)d_in[0];
    const float* k    = (const float*)d_in[1];
    const float* v    = (const float*)d_in[2];
    const int*   mask = (const int*)  d_in[3];
    const float* Wqkv = (const float*)d_in[4];
    const float* bqkv = (const float*)d_in[5];
    const float* Wout = (const float*)d_in[6];
    const float* bout = (const float*)d_in[7];
    float* out = (float*)d_out;

    cudaFuncSetAttribute(mma_gemm<0>, cudaFuncAttributeMaxDynamicSharedMemorySize, GEMM_SMEM);
    cudaFuncSetAttribute(mma_gemm<1>, cudaFuncAttributeMaxDynamicSharedMemorySize, GEMM_SMEM);
    cudaFuncSetAttribute(attn_mma,    cudaFuncAttributeMaxDynamicSharedMemorySize, ATTN_SMEM);

    __nv_bfloat16 *Ahi, *Alo, *Whi, *Wlo, *Chi, *Clo;
    cudaGetSymbolAddress((void**)&Ahi, g_Ahi);
    cudaGetSymbolAddress((void**)&Alo, g_Alo);
    cudaGetSymbolAddress((void**)&Whi, g_Whi);
    cudaGetSymbolAddress((void**)&Wlo, g_Wlo);
    cudaGetSymbolAddress((void**)&Chi, g_Chi);
    cudaGetSymbolAddress((void**)&Clo, g_Clo);

    const int n4 = MT * EE / 4;
    conv_rows3<<<dim3(n4 / 256, 3), 256>>>(q, k, v, Ahi, Alo);

    conv_wT<<<dim3(3 * EE / 32, EE / 32), 256>>>(Wqkv, 3 * EE, Whi, Wlo);
    conv_wT<<<dim3(EE / 32, EE / 32), 256>>>(Wout, EE, Whi + (size_t)3 * EE * EE, Wlo + (size_t)3 * EE * EE);

    mask_bits<<<SS * SS / 1024, 256>>>(mask);

    mma_gemm<0><<<dim3(EE / 128, MT / Bb, 3), 256, GEMM_SMEM>>>(Ahi, Alo, bqkv, nullptr);

    attn_mma<<<dim3(SS / AQ, HH, BB), 256, ATTN_SMEM>>>();

    mma_gemm<1><<<dim3(EE / 128, MT / Bb, 1), 256, GEMM_SMEM>>>(Chi, Clo, bout, out);
}